// round 13
// baseline (speedup 1.0000x reference)
#include <cuda_runtime.h>

#define NN 8192
#define NE 16384
#define DD 128
#define RR 64
#define BB 16
#define GRID 444            // 3 blocks per SM, all co-resident
#define NTHR 256
#define TROWS 64            // rows per work unit
#define WS 64               // sW k-row stride (64-col half, dense)
#define XT 64               // xsT k-row stride (dense, rowpair-packed)

typedef unsigned long long u64;

// ---------------- device scratch (no allocations allowed) ----------------
__device__ __align__(16) float g_fullW[RR*DD*DD];   // 4 MB expanded basis
__device__ int g_comb[NN*RR];                       // (tgt,rel) bucket counts
__device__ int g_cnt8[RR*8];                        // banked relation counters
__device__ int g_off8[RR*8];                        // scanned bank offsets
__device__ int g_relcnt[RR], g_reloff[RR];
__device__ int g_src[NE], g_tgt[NE];
__device__ int g_sorted[NE];
__device__ int g_tiles[1024], g_ntiles;
__device__ int g_is64;
__device__ int g_bar[8];
__device__ int g_sdone, g_bdone, g_scan;
__device__ unsigned g_ticket;

// ---------------- helpers ----------------
__device__ __forceinline__ u64 pack2(float x) {
    u64 r; asm("mov.b64 %0, {%1, %1};" : "=l"(r) : "f"(x)); return r;
}
__device__ __forceinline__ void ffma2(u64& d, u64 a, u64 b) {
    asm("fma.rn.f32x2 %0, %1, %2, %0;" : "+l"(d) : "l"(a), "l"(b));
}
__device__ __forceinline__ float2 unpack2(u64 v) {
    float2 f; asm("mov.b64 {%0, %1}, %2;" : "=f"(f.x), "=f"(f.y) : "l"(v)); return f;
}
__device__ __forceinline__ void red4(float* p, float a, float b, float c, float d) {
    asm volatile("red.global.add.v4.f32 [%0], {%1,%2,%3,%4};"
                 :: "l"(p), "f"(a), "f"(b), "f"(c), "f"(d) : "memory");
}
__device__ __forceinline__ int ld_cg(const int* p) {
    int v; asm volatile("ld.global.cg.b32 %0, [%1];" : "=r"(v) : "l"(p) : "memory"); return v;
}
__device__ __forceinline__ void cpasync16(unsigned dst, const void* src) {
    asm volatile("cp.async.cg.shared.global [%0], [%1], 16;" :: "r"(dst), "l"(src) : "memory");
}
__device__ __forceinline__ void sts2(float* p, float a, float b) {
    asm volatile("st.shared.v2.f32 [%0], {%1,%2};"
                 :: "l"(__cvta_generic_to_shared(p)), "f"(a), "f"(b) : "memory");
}

// ---------------- the single persistent kernel ----------------
__global__ void __launch_bounds__(NTHR, 3) k_fused(
        const float* __restrict__ inp, const void* __restrict__ dep,
        const void* __restrict__ ei,   const float* __restrict__ weight,
        const float* __restrict__ wcomp, const float* __restrict__ sw,
        const float* __restrict__ bias, float* __restrict__ out) {
    extern __shared__ float sm[];
    float* sW    = sm;                    // 128*64 =  8192 floats (W column-half)
    float* xsT   = sm + 8192;             // 128*64 =  8192 floats (rowpair-packed x)
    int*   s_tgt = (int*)(xsT + 8192);
    int*   s_misc= (int*)(s_tgt + TROWS);

    const int bid = blockIdx.x, tid = threadIdx.x;
    const int gtid = bid*NTHR + tid, G = GRID*NTHR;
    const int wid = tid >> 5, lane = tid & 31;

    // ---- phase 0: zero scratch & output, reset flags, quick index-width sniff ----
    {
        const int4 z4 = make_int4(0,0,0,0);
        for (int k = gtid; k < NN*RR/4; k += G) ((int4*)g_comb)[k] = z4;
        const float4 f4 = make_float4(0.f,0.f,0.f,0.f);
        for (int k = gtid; k < NN*DD/4; k += G) ((float4*)out)[k] = f4;
        if (gtid < RR*8) g_cnt8[gtid] = 0;
        if (gtid == 0) { g_ticket = 0u; g_sdone = 0; g_bdone = 0; g_scan = 0; }
        if (bid == 0 && wid == 0) {       // 32-sample sniff: int64 iff all hi words 0
            const unsigned* eu = (const unsigned*)ei;
            unsigned any = (eu[2*lane + 1] != 0u) ? 1u : 0u;
            any = __ballot_sync(0xffffffffu, any);
            if (lane == 0) g_is64 = (any == 0u) ? 1 : 0;
        }
    }
    __threadfence();
    __syncthreads();
    if (tid == 0) {
        atomicAdd(&g_bar[0], 1);
        while (ld_cg(&g_bar[0]) < GRID) __nanosleep(32);
    }
    __syncthreads();

    // ---- fork: blocks 0..63 = edge chain; 64..147 = basis; 148+ = straight to tiles ----
    if (bid < 64) {
        const int e = bid*NTHR + tid;     // 64*256 = 16384 = NE
        int rel, sN, tN;
        if (g_is64) {
            rel = (int)((const long long*)dep)[e];
            sN  = (int)((const long long*)ei)[e];
            tN  = (int)((const long long*)ei)[NE + e];
        } else {
            rel = ((const int*)dep)[e];
            sN  = ((const int*)ei)[e];
            tN  = ((const int*)ei)[NE + e];
        }
        g_src[e] = sN; g_tgt[e] = tN;
        atomicAdd(&g_comb[tN*RR + rel], 1);
        const int bank = bid & 7;
        const int rk = atomicAdd(&g_cnt8[rel*8 + bank], 1);

        __threadfence();
        __syncthreads();
        if (tid == 0) atomicAdd(&g_bar[1], 1);

        if (bid == 0) {
            if (tid == 0) while (ld_cg(&g_bar[1]) < 64) __nanosleep(32);
            __syncthreads();
            if (tid < 32) {                       // parallel scan + tile list
                int vals[16], local = 0;
                #pragma unroll
                for (int k = 0; k < 16; k++) {
                    int c = g_cnt8[tid*16 + k];
                    vals[k] = local; local += c;
                }
                int x = local;
                #pragma unroll
                for (int d = 1; d < 32; d <<= 1) {
                    int y = __shfl_up_sync(0xffffffffu, x, d);
                    if (lane >= d) x += y;
                }
                const int excl = x - local;
                #pragma unroll
                for (int k = 0; k < 16; k++) g_off8[tid*16 + k] = excl + vals[k];
                const int r0 = 2*tid, r1 = 2*tid + 1;
                const int cnt0 = vals[8], cnt1 = local - vals[8];
                g_relcnt[r0] = cnt0; g_relcnt[r1] = cnt1;
                g_reloff[r0] = excl; g_reloff[r1] = excl + vals[8];
                const int nt0 = (cnt0 + TROWS-1)/TROWS, nt1 = (cnt1 + TROWS-1)/TROWS;
                const int ntl = nt0 + nt1;
                int ts = ntl;
                #pragma unroll
                for (int d = 1; d < 32; d <<= 1) {
                    int y = __shfl_up_sync(0xffffffffu, ts, d);
                    if (lane >= d) ts += y;
                }
                const int tbase = ts - ntl;
                for (int c = 0; c < nt0; c++) g_tiles[tbase + c] = (r0 << 8) | c;
                for (int c = 0; c < nt1; c++) g_tiles[tbase + nt0 + c] = (r1 << 8) | c;
                if (tid == 31) g_ntiles = ts;
            }
            __threadfence();
            __syncthreads();
            if (tid == 0) atomicExch(&g_scan, 1);
        } else {
            if (tid == 0) while (ld_cg(&g_scan) == 0) __nanosleep(32);
            __syncthreads();
        }
        g_sorted[g_off8[rel*8 + bank] + rk] = e;
        __threadfence();
        __syncthreads();
        if (tid == 0) atomicAdd(&g_sdone, 1);
    } else if (bid < 148) {
        // basis: 84 blocks over 128 i-planes (first 44 blocks take 2 planes)
        const int j = tid & 127, rh = tid >> 7;          // rh 0..1 -> 32 r's each
        for (int k = tid; k < RR*BB; k += NTHR) sm[k] = wcomp[k];
        __syncthreads();
        const int i1 = bid - 64;
        const int npass = (i1 < 44) ? 2 : 1;
        for (int ps = 0; ps < npass; ps++) {
            const int i = i1 + ps*84;
            float wr[BB];
            #pragma unroll
            for (int b = 0; b < BB; b++) wr[b] = weight[(b*DD + i)*DD + j];
            #pragma unroll 4
            for (int r = rh*32; r < rh*32 + 32; r++) {
                float a = 0.f;
                #pragma unroll
                for (int b = 0; b < BB; b++) a += sm[r*BB + b] * wr[b];
                g_fullW[((size_t)r*DD + i)*DD + j] = a;
            }
        }
        __threadfence();
        __syncthreads();
        if (tid == 0) atomicAdd(&g_bdone, 1);
    }

    // ---- ticket loop over 64-row x 64-col work units ----
    // ticket t: t<256 -> self unit (tile t>>1, col-half t&1); else edge unit.
    // thread tile: 4 rows x 4 cols; warp = rows 8wid..8wid+7, cols = 4*(lane&15).
    const int ty  = 2*wid + (lane >> 4);       // 0..15: rows 4ty..4ty+3
    const int tcl = lane & 15;                 // cols 4tcl..4tcl+3 (within half)
    const unsigned sW_u32 = (unsigned)__cvta_generic_to_shared(sW);
    const float* last_w = (const float*)0;
    int last_ch = -1;
    bool edges_ok = false;
    int ntiles = 0;

    for (;;) {
        __syncthreads();                       // previous unit fully consumed
        if (tid == 0) s_misc[0] = (int)atomicAdd(&g_ticket, 1u);
        __syncthreads();
        const int t = s_misc[0];
        const bool is_self = (t < 2*(NN/TROWS));   // 256 self units

        int rel = 0, base, cnt, off = 0, ch;
        if (is_self) { base = (t >> 1)*TROWS; cnt = NN; ch = t & 1; }
        else {
            if (!edges_ok) {                   // gate: scatter + basis complete
                if (tid == 0)
                    while (ld_cg(&g_sdone) < 64 || ld_cg(&g_bdone) < 84)
                        __nanosleep(64);
                __syncthreads();
                edges_ok = true;
                ntiles = g_ntiles;
            }
            const int u = t - 2*(NN/TROWS);
            if ((u >> 1) >= ntiles) break;
            const int tt = g_tiles[u >> 1];
            ch = u & 1;
            rel = tt >> 8; base = (tt & 255)*TROWS;
            cnt = g_relcnt[rel]; off = g_reloff[rel];
        }

        // ---- stage W column-half (async for edges), overlapped with gather ----
        const float* wsrc = is_self ? sw : g_fullW + (size_t)rel*DD*DD;
        if (wsrc != last_w || ch != last_ch) {
            if (is_self) {                     // transpose sw half on the fly
                #pragma unroll
                for (int p = 0; p < 8; p++) {
                    const int m = tid + p*NTHR;          // < 2048
                    const int jl = m & 63, k4 = m >> 6;  // k4 0..31
                    const float4 v = ((const float4*)sw)[(ch*64 + jl)*32 + k4];
                    sW[(4*k4 + 0)*WS + jl] = v.x;
                    sW[(4*k4 + 1)*WS + jl] = v.y;
                    sW[(4*k4 + 2)*WS + jl] = v.z;
                    sW[(4*k4 + 3)*WS + jl] = v.w;
                }
            } else {                           // dense 32KB half via cp.async
                #pragma unroll
                for (int p = 0; p < 8; p++) {
                    const int m = tid + p*NTHR;          // < 2048
                    const int k = m >> 4, jj = m & 15;
                    cpasync16(sW_u32 + (unsigned)(k*256 + jj*16),
                              (const float4*)wsrc + k*32 + ch*16 + jj);
                }
                asm volatile("cp.async.commit_group;" ::: "memory");
            }
            last_w = wsrc; last_ch = ch;
        }

        // ---- gather x (rowpair-packed, pre-scaled by 1/count) ----
        {
            const int rp = lane, q = wid;      // rows 2rp,2rp+1; k-chunk 16q..16q+15
            int s0, s1; float inv0, inv1;
            if (is_self) {
                s0 = base + 2*rp; s1 = s0 + 1; inv0 = 1.f; inv1 = 1.f;
                if (q == 0) { s_tgt[2*rp] = s0; s_tgt[2*rp + 1] = s1; }
            } else {
                const int le0 = base + 2*rp, le1 = le0 + 1;
                const int e0 = g_sorted[off + (le0 < cnt ? le0 : base)];
                const int e1 = g_sorted[off + (le1 < cnt ? le1 : base)];
                s0 = g_src[e0]; s1 = g_src[e1];
                const int t0 = g_tgt[e0], t1 = g_tgt[e1];
                inv0 = (le0 < cnt) ? 1.0f/(float)g_comb[t0*RR + rel] : 0.f;
                inv1 = (le1 < cnt) ? 1.0f/(float)g_comb[t1*RR + rel] : 0.f;
                if (q == 0) { s_tgt[2*rp] = t0; s_tgt[2*rp + 1] = t1; }
            }
            const float4* ipa = (const float4*)(inp + (size_t)s0*DD);
            const float4* ipb = (const float4*)(inp + (size_t)s1*DD);
            #pragma unroll
            for (int i = 0; i < 4; i++) {
                const int k4 = 4*q + i;
                const float4 va = ipa[k4];
                const float4 vb = ipb[k4];
                float* b0 = xsT + (4*k4)*XT + 2*rp;
                sts2(b0,        va.x*inv0, vb.x*inv1);
                sts2(b0 + XT,   va.y*inv0, vb.y*inv1);
                sts2(b0 + 2*XT, va.z*inv0, vb.z*inv1);
                sts2(b0 + 3*XT, va.w*inv0, vb.w*inv1);
            }
        }
        asm volatile("cp.async.wait_group 0;" ::: "memory");
        __syncthreads();

        // warps whose 8 rows are all past cnt skip compute entirely
        if (is_self || base + 8*wid < cnt) {
            u64 acc[8];                        // [rowpair 0..1][col 0..3]
            #pragma unroll
            for (int q = 0; q < 8; q++) acc[q] = 0ull;

            const float* xp = xsT + 4*ty;      // 1 LDS.128 per k (2 rowpairs)
            const float* wp = sW + 4*tcl;      // 1 LDS.128 per k (4 cols)
            #pragma unroll 4
            for (int k = 0; k < DD; k++) {
                const ulonglong2 xv = *(const ulonglong2*)(xp + k*XT);
                const float4 wv = *(const float4*)(wp + k*WS);
                const u64 w0 = pack2(wv.x), w1 = pack2(wv.y);
                const u64 w2 = pack2(wv.z), w3 = pack2(wv.w);
                ffma2(acc[0], xv.x, w0); ffma2(acc[1], xv.x, w1);
                ffma2(acc[2], xv.x, w2); ffma2(acc[3], xv.x, w3);
                ffma2(acc[4], xv.y, w0); ffma2(acc[5], xv.y, w1);
                ffma2(acc[6], xv.y, w2); ffma2(acc[7], xv.y, w3);
            }

            // epilogue: rows 4ty..4ty+3, cols ch*64 + 4tcl..+3
            float4 bb = make_float4(0.f,0.f,0.f,0.f);
            if (is_self) bb = __ldg((const float4*)bias + ch*16 + tcl);
            const int coff = ch*64 + 4*tcl;
            #pragma unroll
            for (int p = 0; p < 2; p++) {
                const int r0 = 4*ty + 2*p;
                const float2 c0 = unpack2(acc[4*p + 0]);
                const float2 c1 = unpack2(acc[4*p + 1]);
                const float2 c2 = unpack2(acc[4*p + 2]);
                const float2 c3 = unpack2(acc[4*p + 3]);
                red4(out + (size_t)s_tgt[r0]*DD + coff,
                     c0.x + bb.x, c1.x + bb.y, c2.x + bb.z, c3.x + bb.w);
                red4(out + (size_t)s_tgt[r0 + 1]*DD + coff,
                     c0.y + bb.x, c1.y + bb.y, c2.y + bb.z, c3.y + bb.w);
            }
        }
    }

    // ---- epilogue: last block resets barrier slots for graph replay ----
    __threadfence();
    __syncthreads();
    if (tid == 0) {
        const int done = atomicAdd(&g_bar[7], 1);
        if (done == GRID - 1) {
            #pragma unroll
            for (int p = 0; p < 8; p++) g_bar[p] = 0;
            __threadfence();
        }
    }
}

// ---------------- launch ----------------
extern "C" void kernel_launch(void* const* d_in, const int* in_sizes, int n_in,
                              void* d_out, int out_size) {
    const float* inp    = (const float*)d_in[0];
    const void*  dep    = d_in[1];
    const void*  ei     = d_in[2];
    const float* weight = (const float*)d_in[3];
    const float* wcomp  = (const float*)d_in[4];
    const float* sw     = (const float*)d_in[5];
    const float* bias   = (const float*)d_in[6];
    float* out = (float*)d_out;

    const int SMEM = (8192 + 8192 + TROWS + 8) * 4;   // ~64.3 KB -> 3 blocks/SM
    cudaFuncSetAttribute(k_fused, cudaFuncAttributeMaxDynamicSharedMemorySize, SMEM);

    k_fused<<<GRID, NTHR, SMEM>>>(inp, dep, ei, weight, wcomp, sw, bias, out);
}

// round 14
// speedup vs baseline: 1.2106x; 1.2106x over previous
#include <cuda_runtime.h>

#define NN 8192
#define NE 16384
#define DD 128
#define RR 64
#define BB 16
#define GRID 296            // 2 blocks per SM, all co-resident
#define NTHR 256
#define TROWS 64            // rows per tile
#define WS 128              // sW k-row stride (dense, cp.async-friendly)
#define XT 64               // xsT k-row stride (dense, rowpair-packed)

typedef unsigned long long u64;

// ---------------- device scratch (no allocations allowed) ----------------
__device__ __align__(16) float g_fullW[RR*DD*DD];   // 4 MB expanded basis
__device__ int g_comb[NN*RR];                       // (tgt,rel) bucket counts
__device__ int g_cnt8[RR*8];                        // banked relation counters
__device__ int g_off8[RR*8];                        // scanned bank offsets
__device__ int g_relcnt[RR], g_reloff[RR];
__device__ int g_src[NE], g_tgt[NE];
__device__ int g_sorted[NE];
__device__ int g_tiles[1024], g_ntiles;
__device__ int g_is64;
__device__ int g_bar[8];
__device__ int g_sdone, g_bdone, g_scan;
__device__ unsigned g_ticket;

// ---------------- helpers ----------------
__device__ __forceinline__ u64 pack2(float x) {
    u64 r; asm("mov.b64 %0, {%1, %1};" : "=l"(r) : "f"(x)); return r;
}
__device__ __forceinline__ void ffma2(u64& d, u64 a, u64 b) {
    asm("fma.rn.f32x2 %0, %1, %2, %0;" : "+l"(d) : "l"(a), "l"(b));
}
__device__ __forceinline__ float2 unpack2(u64 v) {
    float2 f; asm("mov.b64 {%0, %1}, %2;" : "=f"(f.x), "=f"(f.y) : "l"(v)); return f;
}
__device__ __forceinline__ void red4(float* p, float a, float b, float c, float d) {
    asm volatile("red.global.add.v4.f32 [%0], {%1,%2,%3,%4};"
                 :: "l"(p), "f"(a), "f"(b), "f"(c), "f"(d) : "memory");
}
__device__ __forceinline__ int ld_cg(const int* p) {
    int v; asm volatile("ld.global.cg.b32 %0, [%1];" : "=r"(v) : "l"(p) : "memory"); return v;
}
__device__ __forceinline__ void cpasync16(unsigned dst, const void* src) {
    asm volatile("cp.async.cg.shared.global [%0], [%1], 16;" :: "r"(dst), "l"(src) : "memory");
}
__device__ __forceinline__ void sts2(float* p, float a, float b) {
    asm volatile("st.shared.v2.f32 [%0], {%1,%2};"
                 :: "l"(__cvta_generic_to_shared(p)), "f"(a), "f"(b) : "memory");
}

// ---------------- the single persistent kernel ----------------
__global__ void __launch_bounds__(NTHR, 2) k_fused(
        const float* __restrict__ inp, const void* __restrict__ dep,
        const void* __restrict__ ei,   const float* __restrict__ weight,
        const float* __restrict__ wcomp, const float* __restrict__ sw,
        const float* __restrict__ bias, float* __restrict__ out) {
    extern __shared__ float sm[];
    float* sW    = sm;                    // 129*128 = 16512 floats (row 128 = prefetch pad)
    float* xsT   = sm + 16512;            // 129*64  =  8256 floats (rowpair-packed x)
    int*   s_tgt = (int*)(xsT + 8256);
    int*   s_misc= (int*)(s_tgt + TROWS);

    const int bid = blockIdx.x, tid = threadIdx.x;
    const int gtid = bid*NTHR + tid, G = GRID*NTHR;
    const int wid = tid >> 5, lane = tid & 31;

    // ---- phase 0: zero scratch & output, reset flags, quick index-width sniff ----
    {
        const int4 z4 = make_int4(0,0,0,0);
        for (int k = gtid; k < NN*RR/4; k += G) ((int4*)g_comb)[k] = z4;
        const float4 f4 = make_float4(0.f,0.f,0.f,0.f);
        for (int k = gtid; k < NN*DD/4; k += G) ((float4*)out)[k] = f4;
        if (gtid < RR*8) g_cnt8[gtid] = 0;
        if (gtid == 0) { g_ticket = 0u; g_sdone = 0; g_bdone = 0; g_scan = 0; }
        if (bid == 0 && wid == 0) {       // 32-sample sniff: int64 iff all hi words 0
            const unsigned* eu = (const unsigned*)ei;
            unsigned any = (eu[2*lane + 1] != 0u) ? 1u : 0u;
            any = __ballot_sync(0xffffffffu, any);
            if (lane == 0) g_is64 = (any == 0u) ? 1 : 0;
        }
    }
    __threadfence();
    __syncthreads();
    if (tid == 0) {
        atomicAdd(&g_bar[0], 1);
        while (ld_cg(&g_bar[0]) < GRID) __nanosleep(32);
    }
    __syncthreads();

    // ---- fork: blocks 0..63 = edge chain; 64..147 = basis; 148+ = straight to tiles ----
    if (bid < 64) {
        const int e = bid*NTHR + tid;     // 64*256 = 16384 = NE
        int rel, sN, tN;
        if (g_is64) {
            rel = (int)((const long long*)dep)[e];
            sN  = (int)((const long long*)ei)[e];
            tN  = (int)((const long long*)ei)[NE + e];
        } else {
            rel = ((const int*)dep)[e];
            sN  = ((const int*)ei)[e];
            tN  = ((const int*)ei)[NE + e];
        }
        g_src[e] = sN; g_tgt[e] = tN;
        atomicAdd(&g_comb[tN*RR + rel], 1);
        const int bank = bid & 7;
        const int rk = atomicAdd(&g_cnt8[rel*8 + bank], 1);

        __threadfence();
        __syncthreads();
        if (tid == 0) atomicAdd(&g_bar[1], 1);

        if (bid == 0) {
            if (tid == 0) while (ld_cg(&g_bar[1]) < 64) __nanosleep(32);
            __syncthreads();
            if (tid < 32) {                       // parallel scan + tile list
                int vals[16], local = 0;
                #pragma unroll
                for (int k = 0; k < 16; k++) {
                    int c = g_cnt8[tid*16 + k];
                    vals[k] = local; local += c;
                }
                int x = local;
                #pragma unroll
                for (int d = 1; d < 32; d <<= 1) {
                    int y = __shfl_up_sync(0xffffffffu, x, d);
                    if (lane >= d) x += y;
                }
                const int excl = x - local;
                #pragma unroll
                for (int k = 0; k < 16; k++) g_off8[tid*16 + k] = excl + vals[k];
                const int r0 = 2*tid, r1 = 2*tid + 1;
                const int cnt0 = vals[8], cnt1 = local - vals[8];
                g_relcnt[r0] = cnt0; g_relcnt[r1] = cnt1;
                g_reloff[r0] = excl; g_reloff[r1] = excl + vals[8];
                const int nt0 = (cnt0 + TROWS-1)/TROWS, nt1 = (cnt1 + TROWS-1)/TROWS;
                const int ntl = nt0 + nt1;
                int ts = ntl;
                #pragma unroll
                for (int d = 1; d < 32; d <<= 1) {
                    int y = __shfl_up_sync(0xffffffffu, ts, d);
                    if (lane >= d) ts += y;
                }
                const int tbase = ts - ntl;
                for (int c = 0; c < nt0; c++) g_tiles[tbase + c] = (r0 << 8) | c;
                for (int c = 0; c < nt1; c++) g_tiles[tbase + nt0 + c] = (r1 << 8) | c;
                if (tid == 31) g_ntiles = ts;
            }
            __threadfence();
            __syncthreads();
            if (tid == 0) atomicExch(&g_scan, 1);
        } else {
            if (tid == 0) while (ld_cg(&g_scan) == 0) __nanosleep(32);
            __syncthreads();
        }
        g_sorted[g_off8[rel*8 + bank] + rk] = e;
        __threadfence();
        __syncthreads();
        if (tid == 0) atomicAdd(&g_sdone, 1);
    } else if (bid < 148) {
        // basis: 84 blocks over 128 i-planes (first 44 blocks take 2 planes)
        const int j = tid & 127, rh = tid >> 7;          // rh 0..1 -> 32 r's each
        for (int k = tid; k < RR*BB; k += NTHR) sm[k] = wcomp[k];
        __syncthreads();
        const int i1 = bid - 64;
        const int npass = (i1 < 44) ? 2 : 1;
        for (int ps = 0; ps < npass; ps++) {
            const int i = i1 + ps*84;
            float wr[BB];
            #pragma unroll
            for (int b = 0; b < BB; b++) wr[b] = weight[(b*DD + i)*DD + j];
            #pragma unroll 4
            for (int r = rh*32; r < rh*32 + 32; r++) {
                float a = 0.f;
                #pragma unroll
                for (int b = 0; b < BB; b++) a += sm[r*BB + b] * wr[b];
                g_fullW[((size_t)r*DD + i)*DD + j] = a;
            }
        }
        __threadfence();
        __syncthreads();
        if (tid == 0) atomicAdd(&g_bdone, 1);
    }

    // ---- pipelined ticket loop: self tiles (0..127) first, then gated edges ----
    // thread tile: 8 rows x 4 cols; 256 threads = 8 tr x 32 tc -> 64x128 tile.
    // Deferred epilogue: epilogue(cur) runs while next tile's metadata/W stream.
    const int tr = wid;                        // 0..7: rows 8tr..8tr+7 (warp-uniform)
    const int tc = lane;                       // 0..31: cols 4tc..4tc+3
    const unsigned sW_u32 = (unsigned)__cvta_generic_to_shared(sW);
    const float* last_w = (const float*)0;
    bool edges_ok = false;
    int ntiles = 0;

    u64 acc[16];
    bool have_cur = false, cur_self = false, cur_skip = true;
    int cur_t0[4], cur_t1[4];                  // per-rowpair targets for epilogue

    for (;;) {
        __syncthreads();                       // all warps done with sW/xsT
        if (tid == 0) s_misc[0] = (int)atomicAdd(&g_ticket, 1u);
        __syncthreads();
        const int t = s_misc[0];
        const bool is_self = (t < NN/TROWS);   // 128 self tiles

        int rel = 0, base = 0, cnt = 0, off = 0;
        bool valid = true;
        if (is_self) { base = t*TROWS; cnt = NN; }
        else {
            if (!edges_ok) {                   // gate: scatter + basis complete
                if (tid == 0)
                    while (ld_cg(&g_sdone) < 64 || ld_cg(&g_bdone) < 84)
                        __nanosleep(64);
                __syncthreads();
                edges_ok = true;
                ntiles = g_ntiles;
            }
            if (t - NN/TROWS >= ntiles) valid = false;
            else {
                const int tt = g_tiles[t - NN/TROWS];
                rel = tt >> 8; base = (tt & 255)*TROWS;
                cnt = g_relcnt[rel]; off = g_reloff[rel];
            }
        }

        if (!valid) {                          // drain pending epilogue, exit
            if (have_cur && !cur_skip) {
                float4 bb = make_float4(0.f,0.f,0.f,0.f);
                if (cur_self) bb = __ldg((const float4*)bias + tc);
                #pragma unroll
                for (int rp = 0; rp < 4; rp++) {
                    const float2 c0 = unpack2(acc[4*rp + 0]);
                    const float2 c1 = unpack2(acc[4*rp + 1]);
                    const float2 c2 = unpack2(acc[4*rp + 2]);
                    const float2 c3 = unpack2(acc[4*rp + 3]);
                    red4(out + (size_t)cur_t0[rp]*DD + 4*tc,
                         c0.x + bb.x, c1.x + bb.y, c2.x + bb.z, c3.x + bb.w);
                    red4(out + (size_t)cur_t1[rp]*DD + 4*tc,
                         c0.y + bb.x, c1.y + bb.y, c2.y + bb.z, c3.y + bb.w);
                }
            }
            break;
        }

        // ---- metadata LDG chain for NEXT (left in flight under epilogue) ----
        const int rp_g = lane, q_g = wid;      // gather rows 2rp,2rp+1; k-chunk q
        int s0, s1, t0, t1; float inv0, inv1;
        if (is_self) {
            s0 = base + 2*rp_g; s1 = s0 + 1; t0 = s0; t1 = s1;
            inv0 = 1.f; inv1 = 1.f;
        } else {
            const int le0 = base + 2*rp_g, le1 = le0 + 1;
            const int e0 = g_sorted[off + (le0 < cnt ? le0 : base)];
            const int e1 = g_sorted[off + (le1 < cnt ? le1 : base)];
            s0 = g_src[e0]; s1 = g_src[e1];
            t0 = g_tgt[e0]; t1 = g_tgt[e1];
            inv0 = (le0 < cnt) ? 1.0f/(float)g_comb[t0*RR + rel] : 0.f;
            inv1 = (le1 < cnt) ? 1.0f/(float)g_comb[t1*RR + rel] : 0.f;
        }

        // ---- stage W for NEXT (async for edges) ----
        const float* wsrc = is_self ? sw : g_fullW + (size_t)rel*DD*DD;
        const bool stage_w = (wsrc != last_w);
        if (stage_w && !is_self) {             // dense 64KB via cp.async
            const float4* src4 = (const float4*)wsrc + tid;
            const unsigned d0 = sW_u32 + tid*16;
            #pragma unroll
            for (int p = 0; p < 16; p++)
                cpasync16(d0 + p*4096, src4 + p*256);
            asm volatile("cp.async.commit_group;" ::: "memory");
        }

        // ---- deferred epilogue of CURRENT tile (overlaps metadata/W latency) ----
        if (have_cur && !cur_skip) {
            float4 bb = make_float4(0.f,0.f,0.f,0.f);
            if (cur_self) bb = __ldg((const float4*)bias + tc);
            #pragma unroll
            for (int rp = 0; rp < 4; rp++) {
                const float2 c0 = unpack2(acc[4*rp + 0]);
                const float2 c1 = unpack2(acc[4*rp + 1]);
                const float2 c2 = unpack2(acc[4*rp + 2]);
                const float2 c3 = unpack2(acc[4*rp + 3]);
                red4(out + (size_t)cur_t0[rp]*DD + 4*tc,
                     c0.x + bb.x, c1.x + bb.y, c2.x + bb.z, c3.x + bb.w);
                red4(out + (size_t)cur_t1[rp]*DD + 4*tc,
                     c0.y + bb.x, c1.y + bb.y, c2.y + bb.z, c3.y + bb.w);
            }
        }

        if (stage_w && is_self) {              // transpose sw on the fly (sync STS)
            #pragma unroll
            for (int p = 0; p < 16; p++) {
                const int m = tid + p*NTHR;              // < 4096
                const int jr = m & 127, k4 = m >> 7;
                const float4 v = ((const float4*)sw)[jr*32 + k4];
                sW[(4*k4 + 0)*WS + jr] = v.x;
                sW[(4*k4 + 1)*WS + jr] = v.y;
                sW[(4*k4 + 2)*WS + jr] = v.z;
                sW[(4*k4 + 3)*WS + jr] = v.w;
            }
        }
        if (stage_w) last_w = wsrc;

        // ---- gather x for NEXT (rowpair-packed, pre-scaled) ----
        {
            if (q_g == 0) { s_tgt[2*rp_g] = t0; s_tgt[2*rp_g + 1] = t1; }
            const float4* ipa = (const float4*)(inp + (size_t)s0*DD);
            const float4* ipb = (const float4*)(inp + (size_t)s1*DD);
            #pragma unroll
            for (int i = 0; i < 4; i++) {
                const int k4 = 4*q_g + i;
                const float4 va = ipa[k4];
                const float4 vb = ipb[k4];
                float* b0 = xsT + (4*k4)*XT + 2*rp_g;
                sts2(b0,        va.x*inv0, vb.x*inv1);
                sts2(b0 + XT,   va.y*inv0, vb.y*inv1);
                sts2(b0 + 2*XT, va.z*inv0, vb.z*inv1);
                sts2(b0 + 3*XT, va.w*inv0, vb.w*inv1);
            }
        }
        asm volatile("cp.async.wait_group 0;" ::: "memory");
        __syncthreads();

        // ---- compute NEXT ----
        cur_skip = !(is_self || base + 8*tr < cnt);
        if (!cur_skip) {
            #pragma unroll
            for (int q = 0; q < 16; q++) acc[q] = 0ull;
            const float* xp = xsT + 8*tr;      // 4 u64 per k (broadcast), 16B aligned
            const float* wp = sW + 4*tc;       // 4 floats per k (coalesced 512B)
            ulonglong2 xa = *(const ulonglong2*)xp;
            ulonglong2 xb = *(const ulonglong2*)(xp + 4);
            float4 wv = *(const float4*)wp;
            #pragma unroll 4
            for (int k = 0; k < DD; k++) {
                const ulonglong2 nxa = *(const ulonglong2*)(xp + (k+1)*XT);
                const ulonglong2 nxb = *(const ulonglong2*)(xp + (k+1)*XT + 4);
                const float4 nwv = *(const float4*)(wp + (k+1)*WS);
                const u64 w0 = pack2(wv.x), w1 = pack2(wv.y);
                const u64 w2 = pack2(wv.z), w3 = pack2(wv.w);
                ffma2(acc[ 0], xa.x, w0); ffma2(acc[ 1], xa.x, w1);
                ffma2(acc[ 2], xa.x, w2); ffma2(acc[ 3], xa.x, w3);
                ffma2(acc[ 4], xa.y, w0); ffma2(acc[ 5], xa.y, w1);
                ffma2(acc[ 6], xa.y, w2); ffma2(acc[ 7], xa.y, w3);
                ffma2(acc[ 8], xb.x, w0); ffma2(acc[ 9], xb.x, w1);
                ffma2(acc[10], xb.x, w2); ffma2(acc[11], xb.x, w3);
                ffma2(acc[12], xb.y, w0); ffma2(acc[13], xb.y, w1);
                ffma2(acc[14], xb.y, w2); ffma2(acc[15], xb.y, w3);
                xa = nxa; xb = nxb; wv = nwv;
            }
            #pragma unroll
            for (int rp = 0; rp < 4; rp++) {
                cur_t0[rp] = s_tgt[8*tr + 2*rp];
                cur_t1[rp] = s_tgt[8*tr + 2*rp + 1];
            }
        }
        have_cur = true; cur_self = is_self;
    }

    // ---- epilogue: last block resets barrier slots for graph replay ----
    __threadfence();
    __syncthreads();
    if (tid == 0) {
        const int done = atomicAdd(&g_bar[7], 1);
        if (done == GRID - 1) {
            #pragma unroll
            for (int p = 0; p < 8; p++) g_bar[p] = 0;
            __threadfence();
        }
    }
}

// ---------------- launch ----------------
extern "C" void kernel_launch(void* const* d_in, const int* in_sizes, int n_in,
                              void* d_out, int out_size) {
    const float* inp    = (const float*)d_in[0];
    const void*  dep    = d_in[1];
    const void*  ei     = d_in[2];
    const float* weight = (const float*)d_in[3];
    const float* wcomp  = (const float*)d_in[4];
    const float* sw     = (const float*)d_in[5];
    const float* bias   = (const float*)d_in[6];
    float* out = (float*)d_out;

    const int SMEM = (16512 + 8256 + TROWS + 8) * 4;   // ~97 KB -> 2 blocks/SM
    cudaFuncSetAttribute(k_fused, cudaFuncAttributeMaxDynamicSharedMemorySize, SMEM);

    k_fused<<<GRID, NTHR, SMEM>>>(inp, dep, ei, weight, wcomp, sw, bias, out);
}

// round 15
// speedup vs baseline: 1.2608x; 1.0414x over previous
#include <cuda_runtime.h>

#define NN 8192
#define NE 16384
#define DD 128
#define RR 64
#define BB 16
#define GRID 444            // 3 blocks per SM, all co-resident
#define NTHR 256
#define TROWS 64            // rows per tile
#define KH 64               // k per half-unit
#define WS 128              // sW k-row stride (cols, dense)
#define XT 64               // xsT k-row stride (rowpair-packed)

typedef unsigned long long u64;

// ---------------- device scratch (no allocations allowed) ----------------
__device__ __align__(16) float g_fullW[RR*DD*DD];   // 4 MB expanded basis
__device__ int g_comb[NN*RR];                       // (tgt,rel) bucket counts
__device__ int g_cnt8[RR*8];                        // banked relation counters
__device__ int g_off8[RR*8];                        // scanned bank offsets
__device__ int g_relcnt[RR], g_reloff[RR];
__device__ int g_src[NE], g_tgt[NE];
__device__ int g_sorted[NE];
__device__ int g_tiles[1024], g_ntiles;
__device__ int g_is64;
__device__ int g_bar[8];
__device__ int g_sdone, g_bdone, g_scan;
__device__ unsigned g_ticket;

// ---------------- helpers ----------------
__device__ __forceinline__ u64 pack2(float x) {
    u64 r; asm("mov.b64 %0, {%1, %1};" : "=l"(r) : "f"(x)); return r;
}
__device__ __forceinline__ void ffma2(u64& d, u64 a, u64 b) {
    asm("fma.rn.f32x2 %0, %1, %2, %0;" : "+l"(d) : "l"(a), "l"(b));
}
__device__ __forceinline__ float2 unpack2(u64 v) {
    float2 f; asm("mov.b64 {%0, %1}, %2;" : "=f"(f.x), "=f"(f.y) : "l"(v)); return f;
}
__device__ __forceinline__ void red4(float* p, float a, float b, float c, float d) {
    asm volatile("red.global.add.v4.f32 [%0], {%1,%2,%3,%4};"
                 :: "l"(p), "f"(a), "f"(b), "f"(c), "f"(d) : "memory");
}
__device__ __forceinline__ int ld_cg(const int* p) {
    int v; asm volatile("ld.global.cg.b32 %0, [%1];" : "=r"(v) : "l"(p) : "memory"); return v;
}
__device__ __forceinline__ void cpasync16(unsigned dst, const void* src) {
    asm volatile("cp.async.cg.shared.global [%0], [%1], 16;" :: "r"(dst), "l"(src) : "memory");
}
__device__ __forceinline__ void sts2(float* p, float a, float b) {
    asm volatile("st.shared.v2.f32 [%0], {%1,%2};"
                 :: "l"(__cvta_generic_to_shared(p)), "f"(a), "f"(b) : "memory");
}

// ---------------- the single persistent kernel ----------------
__global__ void __launch_bounds__(NTHR, 3) k_fused(
        const float* __restrict__ inp, const void* __restrict__ dep,
        const void* __restrict__ ei,   const float* __restrict__ weight,
        const float* __restrict__ wcomp, const float* __restrict__ sw,
        const float* __restrict__ bias, float* __restrict__ out) {
    extern __shared__ float sm[];
    float* sW    = sm;                    // KH*128 =  8192 floats (W k-half)
    float* xsT   = sm + 8192;             // KH*64  =  4096 floats (x k-half)
    int*   s_tgt = (int*)(xsT + 4096);
    int*   s_misc= (int*)(s_tgt + TROWS);

    const int bid = blockIdx.x, tid = threadIdx.x;
    const int gtid = bid*NTHR + tid, G = GRID*NTHR;
    const int wid = tid >> 5, lane = tid & 31;

    // ---- phase 0: zero scratch & output, reset flags, quick index-width sniff ----
    {
        const int4 z4 = make_int4(0,0,0,0);
        for (int k = gtid; k < NN*RR/4; k += G) ((int4*)g_comb)[k] = z4;
        const float4 f4 = make_float4(0.f,0.f,0.f,0.f);
        for (int k = gtid; k < NN*DD/4; k += G) ((float4*)out)[k] = f4;
        if (gtid < RR*8) g_cnt8[gtid] = 0;
        if (gtid == 0) { g_ticket = 0u; g_sdone = 0; g_bdone = 0; g_scan = 0; }
        if (bid == 0 && wid == 0) {       // 32-sample sniff: int64 iff all hi words 0
            const unsigned* eu = (const unsigned*)ei;
            unsigned any = (eu[2*lane + 1] != 0u) ? 1u : 0u;
            any = __ballot_sync(0xffffffffu, any);
            if (lane == 0) g_is64 = (any == 0u) ? 1 : 0;
        }
    }
    __threadfence();
    __syncthreads();
    if (tid == 0) {
        atomicAdd(&g_bar[0], 1);
        while (ld_cg(&g_bar[0]) < GRID) __nanosleep(32);
    }
    __syncthreads();

    // ---- fork: blocks 0..63 = edge chain; 64..147 = basis; 148+ = straight to tiles ----
    if (bid < 64) {
        const int e = bid*NTHR + tid;     // 64*256 = 16384 = NE
        int rel, sN, tN;
        if (g_is64) {
            rel = (int)((const long long*)dep)[e];
            sN  = (int)((const long long*)ei)[e];
            tN  = (int)((const long long*)ei)[NE + e];
        } else {
            rel = ((const int*)dep)[e];
            sN  = ((const int*)ei)[e];
            tN  = ((const int*)ei)[NE + e];
        }
        g_src[e] = sN; g_tgt[e] = tN;
        atomicAdd(&g_comb[tN*RR + rel], 1);
        const int bank = bid & 7;
        const int rk = atomicAdd(&g_cnt8[rel*8 + bank], 1);

        __threadfence();
        __syncthreads();
        if (tid == 0) atomicAdd(&g_bar[1], 1);

        if (bid == 0) {
            if (tid == 0) while (ld_cg(&g_bar[1]) < 64) __nanosleep(32);
            __syncthreads();
            if (tid < 32) {                       // parallel scan + tile list
                int vals[16], local = 0;
                #pragma unroll
                for (int k = 0; k < 16; k++) {
                    int c = g_cnt8[tid*16 + k];
                    vals[k] = local; local += c;
                }
                int x = local;
                #pragma unroll
                for (int d = 1; d < 32; d <<= 1) {
                    int y = __shfl_up_sync(0xffffffffu, x, d);
                    if (lane >= d) x += y;
                }
                const int excl = x - local;
                #pragma unroll
                for (int k = 0; k < 16; k++) g_off8[tid*16 + k] = excl + vals[k];
                const int r0 = 2*tid, r1 = 2*tid + 1;
                const int cnt0 = vals[8], cnt1 = local - vals[8];
                g_relcnt[r0] = cnt0; g_relcnt[r1] = cnt1;
                g_reloff[r0] = excl; g_reloff[r1] = excl + vals[8];
                const int nt0 = (cnt0 + TROWS-1)/TROWS, nt1 = (cnt1 + TROWS-1)/TROWS;
                const int ntl = nt0 + nt1;
                int ts = ntl;
                #pragma unroll
                for (int d = 1; d < 32; d <<= 1) {
                    int y = __shfl_up_sync(0xffffffffu, ts, d);
                    if (lane >= d) ts += y;
                }
                const int tbase = ts - ntl;
                for (int c = 0; c < nt0; c++) g_tiles[tbase + c] = (r0 << 8) | c;
                for (int c = 0; c < nt1; c++) g_tiles[tbase + nt0 + c] = (r1 << 8) | c;
                if (tid == 31) g_ntiles = ts;
            }
            __threadfence();
            __syncthreads();
            if (tid == 0) atomicExch(&g_scan, 1);
        } else {
            if (tid == 0) while (ld_cg(&g_scan) == 0) __nanosleep(32);
            __syncthreads();
        }
        g_sorted[g_off8[rel*8 + bank] + rk] = e;
        __threadfence();
        __syncthreads();
        if (tid == 0) atomicAdd(&g_sdone, 1);
    } else if (bid < 148) {
        // basis: 84 blocks over 128 i-planes (first 44 blocks take 2 planes)
        const int j = tid & 127, rh = tid >> 7;          // rh 0..1 -> 32 r's each
        for (int k = tid; k < RR*BB; k += NTHR) sm[k] = wcomp[k];
        __syncthreads();
        const int i1 = bid - 64;
        const int npass = (i1 < 44) ? 2 : 1;
        for (int ps = 0; ps < npass; ps++) {
            const int i = i1 + ps*84;
            float wr[BB];
            #pragma unroll
            for (int b = 0; b < BB; b++) wr[b] = weight[(b*DD + i)*DD + j];
            #pragma unroll 4
            for (int r = rh*32; r < rh*32 + 32; r++) {
                float a = 0.f;
                #pragma unroll
                for (int b = 0; b < BB; b++) a += sm[r*BB + b] * wr[b];
                g_fullW[((size_t)r*DD + i)*DD + j] = a;
            }
        }
        __threadfence();
        __syncthreads();
        if (tid == 0) atomicAdd(&g_bdone, 1);
    }

    // ---- ticket loop over 64-row x 128-col x 64-k half-units ----
    // unit t: t<256 -> self (tile t>>1, khalf t&1); else edge (g_tiles[(t-256)>>1]).
    // thread tile: 8 rows x 4 cols; bare loop (TLP hides latency, 24 warps/SM).
    const int tr = wid;                        // 0..7: rows 8tr..8tr+7 (warp-uniform)
    const int tc = lane;                       // 0..31: cols 4tc..4tc+3
    const unsigned sW_u32 = (unsigned)__cvta_generic_to_shared(sW);
    const float* last_w = (const float*)0;
    int last_ch = -1;
    bool edges_ok = false;
    int ntiles = 0;

    for (;;) {
        __syncthreads();                       // previous unit fully consumed
        if (tid == 0) s_misc[0] = (int)atomicAdd(&g_ticket, 1u);
        __syncthreads();
        const int t = s_misc[0];
        const bool is_self = (t < 2*(NN/TROWS)*0 + 256);   // 256 self units

        int rel = 0, base, cnt, off = 0, ch;
        if (is_self) { base = (t >> 1)*TROWS; cnt = NN; ch = t & 1; }
        else {
            if (!edges_ok) {                   // gate: scatter + basis complete
                if (tid == 0)
                    while (ld_cg(&g_sdone) < 64 || ld_cg(&g_bdone) < 84)
                        __nanosleep(64);
                __syncthreads();
                edges_ok = true;
                ntiles = g_ntiles;
            }
            const int u = t - 256;
            if ((u >> 1) >= ntiles) break;
            const int tt = g_tiles[u >> 1];
            ch = u & 1;
            rel = tt >> 8; base = (tt & 255)*TROWS;
            cnt = g_relcnt[rel]; off = g_reloff[rel];
        }

        // ---- stage W k-half (async for edges), overlapped with the gather ----
        const float* wsrc = is_self ? sw : g_fullW + (size_t)rel*DD*DD;
        if (wsrc != last_w || ch != last_ch) {
            if (!is_self) {                    // dense 32KB half via cp.async
                const float4* src4 = (const float4*)wsrc + ch*(KH*32) + tid;
                const unsigned d0 = sW_u32 + tid*16;
                #pragma unroll
                for (int p = 0; p < 8; p++)
                    cpasync16(d0 + p*4096, src4 + p*256);
                asm volatile("cp.async.commit_group;" ::: "memory");
            } else {                           // transpose sw k-half on the fly
                #pragma unroll
                for (int p = 0; p < 8; p++) {
                    const int m = tid + p*NTHR;          // < 2048
                    const int jr = m & 127, k4 = m >> 7;  // k4 0..15
                    const float4 v = ((const float4*)sw)[jr*32 + ch*16 + k4];
                    sW[(4*k4 + 0)*WS + jr] = v.x;
                    sW[(4*k4 + 1)*WS + jr] = v.y;
                    sW[(4*k4 + 2)*WS + jr] = v.z;
                    sW[(4*k4 + 3)*WS + jr] = v.w;
                }
            }
            last_w = wsrc; last_ch = ch;
        }

        // ---- gather x k-half (rowpair-packed, pre-scaled by 1/count) ----
        {
            const int rp = lane, q = wid;      // rows 2rp,2rp+1; k4-pair 2q..2q+1
            int s0, s1; float inv0, inv1;
            if (is_self) {
                s0 = base + 2*rp; s1 = s0 + 1; inv0 = 1.f; inv1 = 1.f;
                if (q == 0) { s_tgt[2*rp] = s0; s_tgt[2*rp + 1] = s1; }
            } else {
                const int le0 = base + 2*rp, le1 = le0 + 1;
                const int e0 = g_sorted[off + (le0 < cnt ? le0 : base)];
                const int e1 = g_sorted[off + (le1 < cnt ? le1 : base)];
                s0 = g_src[e0]; s1 = g_src[e1];
                const int t0 = g_tgt[e0], t1 = g_tgt[e1];
                inv0 = (le0 < cnt) ? 1.0f/(float)g_comb[t0*RR + rel] : 0.f;
                inv1 = (le1 < cnt) ? 1.0f/(float)g_comb[t1*RR + rel] : 0.f;
                if (q == 0) { s_tgt[2*rp] = t0; s_tgt[2*rp + 1] = t1; }
            }
            const float4* ipa = (const float4*)(inp + (size_t)s0*DD) + ch*16;
            const float4* ipb = (const float4*)(inp + (size_t)s1*DD) + ch*16;
            #pragma unroll
            for (int i = 0; i < 2; i++) {
                const int k4 = 2*q + i;                  // 0..15 within half
                const float4 va = ipa[k4];
                const float4 vb = ipb[k4];
                float* b0 = xsT + (4*k4)*XT + 2*rp;
                sts2(b0,        va.x*inv0, vb.x*inv1);
                sts2(b0 + XT,   va.y*inv0, vb.y*inv1);
                sts2(b0 + 2*XT, va.z*inv0, vb.z*inv1);
                sts2(b0 + 3*XT, va.w*inv0, vb.w*inv1);
            }
        }
        asm volatile("cp.async.wait_group 0;" ::: "memory");
        __syncthreads();

        // warps whose 8 rows are all past cnt skip compute entirely
        if (is_self || base + 8*tr < cnt) {
            u64 acc[16];                       // [rowpair rp 0..3][col c 0..3]
            #pragma unroll
            for (int q = 0; q < 16; q++) acc[q] = 0ull;

            const float* xp = xsT + 8*tr;      // 2 LDS.128 per k (broadcast)
            const float* wp = sW + 4*tc;       // 1 LDS.128 per k (coalesced)
            #pragma unroll 4
            for (int k = 0; k < KH; k++) {
                const ulonglong2 xa = *(const ulonglong2*)(xp + k*XT);
                const ulonglong2 xb = *(const ulonglong2*)(xp + k*XT + 4);
                const float4 wv = *(const float4*)(wp + k*WS);
                const u64 w0 = pack2(wv.x), w1 = pack2(wv.y);
                const u64 w2 = pack2(wv.z), w3 = pack2(wv.w);
                ffma2(acc[ 0], xa.x, w0); ffma2(acc[ 1], xa.x, w1);
                ffma2(acc[ 2], xa.x, w2); ffma2(acc[ 3], xa.x, w3);
                ffma2(acc[ 4], xa.y, w0); ffma2(acc[ 5], xa.y, w1);
                ffma2(acc[ 6], xa.y, w2); ffma2(acc[ 7], xa.y, w3);
                ffma2(acc[ 8], xb.x, w0); ffma2(acc[ 9], xb.x, w1);
                ffma2(acc[10], xb.x, w2); ffma2(acc[11], xb.x, w3);
                ffma2(acc[12], xb.y, w0); ffma2(acc[13], xb.y, w1);
                ffma2(acc[14], xb.y, w2); ffma2(acc[15], xb.y, w3);
            }

            // epilogue: bias only from k-half 0 of self tiles
            float4 bb = make_float4(0.f,0.f,0.f,0.f);
            if (is_self && ch == 0) bb = __ldg((const float4*)bias + tc);
            #pragma unroll
            for (int rp = 0; rp < 4; rp++) {
                const int r0 = 8*tr + 2*rp;
                const float2 c0 = unpack2(acc[4*rp + 0]);
                const float2 c1 = unpack2(acc[4*rp + 1]);
                const float2 c2 = unpack2(acc[4*rp + 2]);
                const float2 c3 = unpack2(acc[4*rp + 3]);
                red4(out + (size_t)s_tgt[r0]*DD + 4*tc,
                     c0.x + bb.x, c1.x + bb.y, c2.x + bb.z, c3.x + bb.w);
                red4(out + (size_t)s_tgt[r0 + 1]*DD + 4*tc,
                     c0.y + bb.x, c1.y + bb.y, c2.y + bb.z, c3.y + bb.w);
            }
        }
    }

    // ---- epilogue: last block resets barrier slots for graph replay ----
    __threadfence();
    __syncthreads();
    if (tid == 0) {
        const int done = atomicAdd(&g_bar[7], 1);
        if (done == GRID - 1) {
            #pragma unroll
            for (int p = 0; p < 8; p++) g_bar[p] = 0;
            __threadfence();
        }
    }
}

// ---------------- launch ----------------
extern "C" void kernel_launch(void* const* d_in, const int* in_sizes, int n_in,
                              void* d_out, int out_size) {
    const float* inp    = (const float*)d_in[0];
    const void*  dep    = d_in[1];
    const void*  ei     = d_in[2];
    const float* weight = (const float*)d_in[3];
    const float* wcomp  = (const float*)d_in[4];
    const float* sw     = (const float*)d_in[5];
    const float* bias   = (const float*)d_in[6];
    float* out = (float*)d_out;

    const int SMEM = (8192 + 4096 + TROWS + 8) * 4;   // ~48.4 KB -> 3 blocks/SM
    cudaFuncSetAttribute(k_fused, cudaFuncAttributeMaxDynamicSharedMemorySize, SMEM);

    k_fused<<<GRID, NTHR, SMEM>>>(inp, dep, ei, weight, wcomp, sw, bias, out);
}

// round 16
// speedup vs baseline: 1.3288x; 1.0539x over previous
#include <cuda_runtime.h>

#define NN 8192
#define NE 16384
#define DD 128
#define RR 64
#define BB 16
#define GRID 444            // 3 blocks per SM, all co-resident
#define NTHR 256
#define TROWS 64            // rows per tile
#define KH 64               // k per half-unit
#define WS 128              // sW k-row stride (cols, dense)
#define XT 64               // xsT k-row stride (rowpair-packed)

typedef unsigned long long u64;

// ---------------- device scratch (no allocations allowed) ----------------
__device__ __align__(16) float g_fullW[RR*DD*DD];   // 4 MB expanded basis
__device__ int g_comb[NN*RR];                       // (tgt,rel) bucket counts
__device__ int g_cnt8[RR*8];                        // banked relation counters
__device__ int g_off8[RR*8];                        // scanned bank offsets
__device__ int g_relcnt[RR], g_reloff[RR];
__device__ int g_src[NE], g_tgt[NE];
__device__ __align__(16) int4 g_pack[NE];           // sorted {src, tgt, inv_bits, 0}
__device__ int g_tiles[1024], g_ntiles;
__device__ int g_is64;
__device__ int g_bar[8];
__device__ int g_sdone, g_bdone, g_scan;
__device__ unsigned g_ticket;

// ---------------- helpers ----------------
__device__ __forceinline__ u64 pack2(float x) {
    u64 r; asm("mov.b64 %0, {%1, %1};" : "=l"(r) : "f"(x)); return r;
}
__device__ __forceinline__ void ffma2(u64& d, u64 a, u64 b) {
    asm("fma.rn.f32x2 %0, %1, %2, %0;" : "+l"(d) : "l"(a), "l"(b));
}
__device__ __forceinline__ float2 unpack2(u64 v) {
    float2 f; asm("mov.b64 {%0, %1}, %2;" : "=f"(f.x), "=f"(f.y) : "l"(v)); return f;
}
__device__ __forceinline__ void red4(float* p, float a, float b, float c, float d) {
    asm volatile("red.global.add.v4.f32 [%0], {%1,%2,%3,%4};"
                 :: "l"(p), "f"(a), "f"(b), "f"(c), "f"(d) : "memory");
}
__device__ __forceinline__ int ld_cg(const int* p) {
    int v; asm volatile("ld.global.cg.b32 %0, [%1];" : "=r"(v) : "l"(p) : "memory"); return v;
}
__device__ __forceinline__ void cpasync16(unsigned dst, const void* src) {
    asm volatile("cp.async.cg.shared.global [%0], [%1], 16;" :: "r"(dst), "l"(src) : "memory");
}
__device__ __forceinline__ void sts2(float* p, float a, float b) {
    asm volatile("st.shared.v2.f32 [%0], {%1,%2};"
                 :: "l"(__cvta_generic_to_shared(p)), "f"(a), "f"(b) : "memory");
}

// ---------------- the single persistent kernel ----------------
__global__ void __launch_bounds__(NTHR, 3) k_fused(
        const float* __restrict__ inp, const void* __restrict__ dep,
        const void* __restrict__ ei,   const float* __restrict__ weight,
        const float* __restrict__ wcomp, const float* __restrict__ sw,
        const float* __restrict__ bias, float* __restrict__ out) {
    extern __shared__ float sm[];
    float* sW    = sm;                    // KH*128 =  8192 floats (W k-half)
    float* xsT   = sm + 8192;             // KH*64  =  4096 floats (x k-half)
    int*   s_tgt = (int*)(xsT + 4096);
    int*   s_misc= (int*)(s_tgt + TROWS);

    const int bid = blockIdx.x, tid = threadIdx.x;
    const int gtid = bid*NTHR + tid, G = GRID*NTHR;
    const int wid = tid >> 5, lane = tid & 31;

    // ---- phase 0: zero scratch & output, reset flags, quick index-width sniff ----
    {
        const int4 z4 = make_int4(0,0,0,0);
        for (int k = gtid; k < NN*RR/4; k += G) ((int4*)g_comb)[k] = z4;
        const float4 f4 = make_float4(0.f,0.f,0.f,0.f);
        for (int k = gtid; k < NN*DD/4; k += G) ((float4*)out)[k] = f4;
        if (gtid < RR*8) g_cnt8[gtid] = 0;
        if (gtid == 0) { g_ticket = 0u; g_sdone = 0; g_bdone = 0; g_scan = 0; }
        if (bid == 0 && wid == 0) {       // 32-sample sniff: int64 iff all hi words 0
            const unsigned* eu = (const unsigned*)ei;
            unsigned any = (eu[2*lane + 1] != 0u) ? 1u : 0u;
            any = __ballot_sync(0xffffffffu, any);
            if (lane == 0) g_is64 = (any == 0u) ? 1 : 0;
        }
    }
    __threadfence();
    __syncthreads();
    if (tid == 0) {
        atomicAdd(&g_bar[0], 1);
        while (ld_cg(&g_bar[0]) < GRID) __nanosleep(32);
    }
    __syncthreads();

    // ---- fork: blocks 0..63 = edge chain; 64..147 = basis; 148+ = straight to tiles ----
    if (bid < 64) {
        const int e = bid*NTHR + tid;     // 64*256 = 16384 = NE
        int rel, sN, tN;
        if (g_is64) {
            rel = (int)((const long long*)dep)[e];
            sN  = (int)((const long long*)ei)[e];
            tN  = (int)((const long long*)ei)[NE + e];
        } else {
            rel = ((const int*)dep)[e];
            sN  = ((const int*)ei)[e];
            tN  = ((const int*)ei)[NE + e];
        }
        g_src[e] = sN; g_tgt[e] = tN;
        atomicAdd(&g_comb[tN*RR + rel], 1);
        const int bank = bid & 7;
        const int rk = atomicAdd(&g_cnt8[rel*8 + bank], 1);

        __threadfence();
        __syncthreads();
        if (tid == 0) atomicAdd(&g_bar[1], 1);

        if (bid == 0) {
            if (tid == 0) while (ld_cg(&g_bar[1]) < 64) __nanosleep(32);
            __syncthreads();
            if (tid < 32) {                       // parallel scan + tile list
                int vals[16], local = 0;
                #pragma unroll
                for (int k = 0; k < 16; k++) {
                    int c = g_cnt8[tid*16 + k];
                    vals[k] = local; local += c;
                }
                int x = local;
                #pragma unroll
                for (int d = 1; d < 32; d <<= 1) {
                    int y = __shfl_up_sync(0xffffffffu, x, d);
                    if (lane >= d) x += y;
                }
                const int excl = x - local;
                #pragma unroll
                for (int k = 0; k < 16; k++) g_off8[tid*16 + k] = excl + vals[k];
                const int r0 = 2*tid, r1 = 2*tid + 1;
                const int cnt0 = vals[8], cnt1 = local - vals[8];
                g_relcnt[r0] = cnt0; g_relcnt[r1] = cnt1;
                g_reloff[r0] = excl; g_reloff[r1] = excl + vals[8];
                const int nt0 = (cnt0 + TROWS-1)/TROWS, nt1 = (cnt1 + TROWS-1)/TROWS;
                const int ntl = nt0 + nt1;
                int ts = ntl;
                #pragma unroll
                for (int d = 1; d < 32; d <<= 1) {
                    int y = __shfl_up_sync(0xffffffffu, ts, d);
                    if (lane >= d) ts += y;
                }
                const int tbase = ts - ntl;
                for (int c = 0; c < nt0; c++) g_tiles[tbase + c] = (r0 << 8) | c;
                for (int c = 0; c < nt1; c++) g_tiles[tbase + nt0 + c] = (r1 << 8) | c;
                if (tid == 31) g_ntiles = ts;
            }
            __threadfence();
            __syncthreads();
            if (tid == 0) atomicExch(&g_scan, 1);
        } else {
            if (tid == 0) while (ld_cg(&g_scan) == 0) __nanosleep(32);
            __syncthreads();
        }
        // scatter packed descriptor: counts are final here
        {
            const float inv = 1.0f/(float)g_comb[tN*RR + rel];
            g_pack[g_off8[rel*8 + bank] + rk] =
                make_int4(sN, tN, __float_as_int(inv), 0);
        }
        __threadfence();
        __syncthreads();
        if (tid == 0) atomicAdd(&g_sdone, 1);
    } else if (bid < 148) {
        // basis: 84 blocks over 128 i-planes (first 44 blocks take 2 planes)
        const int j = tid & 127, rh = tid >> 7;          // rh 0..1 -> 32 r's each
        for (int k = tid; k < RR*BB; k += NTHR) sm[k] = wcomp[k];
        __syncthreads();
        const int i1 = bid - 64;
        const int npass = (i1 < 44) ? 2 : 1;
        for (int ps = 0; ps < npass; ps++) {
            const int i = i1 + ps*84;
            float wr[BB];
            #pragma unroll
            for (int b = 0; b < BB; b++) wr[b] = weight[(b*DD + i)*DD + j];
            #pragma unroll 4
            for (int r = rh*32; r < rh*32 + 32; r++) {
                float a = 0.f;
                #pragma unroll
                for (int b = 0; b < BB; b++) a += sm[r*BB + b] * wr[b];
                g_fullW[((size_t)r*DD + i)*DD + j] = a;
            }
        }
        __threadfence();
        __syncthreads();
        if (tid == 0) atomicAdd(&g_bdone, 1);
    }

    // ---- ticket loop over 64-row x 128-col x 64-k half-units (ch-major) ----
    // self: t in [0,128) -> ch0 tile t;  [128,256) -> ch1 tile t-128.
    // edge: u = t-256; u < ntiles -> ch0 tile u; else ch1 tile u-ntiles.
    const int tr = wid;                        // 0..7: rows 8tr..8tr+7 (warp-uniform)
    const int tc = lane;                       // 0..31: cols 4tc..4tc+3
    const unsigned sW_u32 = (unsigned)__cvta_generic_to_shared(sW);
    const float* last_w = (const float*)0;
    int last_ch = -1;
    bool edges_ok = false;
    int ntiles = 0;

    for (;;) {
        __syncthreads();                       // previous unit fully consumed
        if (tid == 0) s_misc[0] = (int)atomicAdd(&g_ticket, 1u);
        __syncthreads();
        const int t = s_misc[0];
        const bool is_self = (t < 256);

        int rel = 0, base, cnt, off = 0, ch;
        if (is_self) { ch = t >> 7; base = (t & 127)*TROWS; cnt = NN; }
        else {
            if (!edges_ok) {                   // gate: scatter + basis complete
                if (tid == 0)
                    while (ld_cg(&g_sdone) < 64 || ld_cg(&g_bdone) < 84)
                        __nanosleep(64);
                __syncthreads();
                edges_ok = true;
                ntiles = g_ntiles;
            }
            const int u = t - 256;
            if (u >= 2*ntiles) break;
            ch = (u >= ntiles) ? 1 : 0;
            const int tt = g_tiles[ch ? u - ntiles : u];
            rel = tt >> 8; base = (tt & 255)*TROWS;
            cnt = g_relcnt[rel]; off = g_reloff[rel];
        }

        // ---- stage W k-half (async for edges), overlapped with the gather ----
        const float* wsrc = is_self ? sw : g_fullW + (size_t)rel*DD*DD;
        if (wsrc != last_w || ch != last_ch) {
            if (!is_self) {                    // dense 32KB half via cp.async
                const float4* src4 = (const float4*)wsrc + ch*(KH*32) + tid;
                const unsigned d0 = sW_u32 + tid*16;
                #pragma unroll
                for (int p = 0; p < 8; p++)
                    cpasync16(d0 + p*4096, src4 + p*256);
                asm volatile("cp.async.commit_group;" ::: "memory");
            } else {                           // transpose sw k-half on the fly
                #pragma unroll
                for (int p = 0; p < 8; p++) {
                    const int m = tid + p*NTHR;          // < 2048
                    const int jr = m & 127, k4 = m >> 7;  // k4 0..15
                    const float4 v = ((const float4*)sw)[jr*32 + ch*16 + k4];
                    sW[(4*k4 + 0)*WS + jr] = v.x;
                    sW[(4*k4 + 1)*WS + jr] = v.y;
                    sW[(4*k4 + 2)*WS + jr] = v.z;
                    sW[(4*k4 + 3)*WS + jr] = v.w;
                }
            }
            last_w = wsrc; last_ch = ch;
        }

        // ---- gather x k-half (rowpair-packed, pre-scaled by 1/count) ----
        {
            const int rp = lane, q = wid;      // rows 2rp,2rp+1; k4-pair 2q..2q+1
            int s0, s1; float inv0, inv1;
            if (is_self) {
                s0 = base + 2*rp; s1 = s0 + 1; inv0 = 1.f; inv1 = 1.f;
                if (q == 0) { s_tgt[2*rp] = s0; s_tgt[2*rp + 1] = s1; }
            } else {
                const int le0 = base + 2*rp, le1 = le0 + 1;
                const int4 p0 = g_pack[off + (le0 < cnt ? le0 : base)];
                const int4 p1 = g_pack[off + (le1 < cnt ? le1 : base)];
                s0 = p0.x; s1 = p1.x;
                inv0 = (le0 < cnt) ? __int_as_float(p0.z) : 0.f;
                inv1 = (le1 < cnt) ? __int_as_float(p1.z) : 0.f;
                if (q == 0) { s_tgt[2*rp] = p0.y; s_tgt[2*rp + 1] = p1.y; }
            }
            const float4* ipa = (const float4*)(inp + (size_t)s0*DD) + ch*16;
            const float4* ipb = (const float4*)(inp + (size_t)s1*DD) + ch*16;
            #pragma unroll
            for (int i = 0; i < 2; i++) {
                const int k4 = 2*q + i;                  // 0..15 within half
                const float4 va = ipa[k4];
                const float4 vb = ipb[k4];
                float* b0 = xsT + (4*k4)*XT + 2*rp;
                sts2(b0,        va.x*inv0, vb.x*inv1);
                sts2(b0 + XT,   va.y*inv0, vb.y*inv1);
                sts2(b0 + 2*XT, va.z*inv0, vb.z*inv1);
                sts2(b0 + 3*XT, va.w*inv0, vb.w*inv1);
            }
        }
        asm volatile("cp.async.wait_group 0;" ::: "memory");
        __syncthreads();

        // warps whose 8 rows are all past cnt skip compute entirely
        if (is_self || base + 8*tr < cnt) {
            u64 acc[16];                       // [rowpair rp 0..3][col c 0..3]
            #pragma unroll
            for (int q = 0; q < 16; q++) acc[q] = 0ull;

            const float* xp = xsT + 8*tr;      // 2 LDS.128 per k (broadcast)
            const float* wp = sW + 4*tc;       // 1 LDS.128 per k (coalesced)
            #pragma unroll 4
            for (int k = 0; k < KH; k++) {
                const ulonglong2 xa = *(const ulonglong2*)(xp + k*XT);
                const ulonglong2 xb = *(const ulonglong2*)(xp + k*XT + 4);
                const float4 wv = *(const float4*)(wp + k*WS);
                const u64 w0 = pack2(wv.x), w1 = pack2(wv.y);
                const u64 w2 = pack2(wv.z), w3 = pack2(wv.w);
                ffma2(acc[ 0], xa.x, w0); ffma2(acc[ 1], xa.x, w1);
                ffma2(acc[ 2], xa.x, w2); ffma2(acc[ 3], xa.x, w3);
                ffma2(acc[ 4], xa.y, w0); ffma2(acc[ 5], xa.y, w1);
                ffma2(acc[ 6], xa.y, w2); ffma2(acc[ 7], xa.y, w3);
                ffma2(acc[ 8], xb.x, w0); ffma2(acc[ 9], xb.x, w1);
                ffma2(acc[10], xb.x, w2); ffma2(acc[11], xb.x, w3);
                ffma2(acc[12], xb.y, w0); ffma2(acc[13], xb.y, w1);
                ffma2(acc[14], xb.y, w2); ffma2(acc[15], xb.y, w3);
            }

            // epilogue: bias only from k-half 0 of self tiles
            float4 bb = make_float4(0.f,0.f,0.f,0.f);
            if (is_self && ch == 0) bb = __ldg((const float4*)bias + tc);
            #pragma unroll
            for (int rp = 0; rp < 4; rp++) {
                const int r0 = 8*tr + 2*rp;
                const float2 c0 = unpack2(acc[4*rp + 0]);
                const float2 c1 = unpack2(acc[4*rp + 1]);
                const float2 c2 = unpack2(acc[4*rp + 2]);
                const float2 c3 = unpack2(acc[4*rp + 3]);
                red4(out + (size_t)s_tgt[r0]*DD + 4*tc,
                     c0.x + bb.x, c1.x + bb.y, c2.x + bb.z, c3.x + bb.w);
                red4(out + (size_t)s_tgt[r0 + 1]*DD + 4*tc,
                     c0.y + bb.x, c1.y + bb.y, c2.y + bb.z, c3.y + bb.w);
            }
        }
    }

    // ---- epilogue: last block resets barrier slots for graph replay ----
    __threadfence();
    __syncthreads();
    if (tid == 0) {
        const int done = atomicAdd(&g_bar[7], 1);
        if (done == GRID - 1) {
            #pragma unroll
            for (int p = 0; p < 8; p++) g_bar[p] = 0;
            __threadfence();
        }
    }
}

// ---------------- launch ----------------
extern "C" void kernel_launch(void* const* d_in, const int* in_sizes, int n_in,
                              void* d_out, int out_size) {
    const float* inp    = (const float*)d_in[0];
    const void*  dep    = d_in[1];
    const void*  ei     = d_in[2];
    const float* weight = (const float*)d_in[3];
    const float* wcomp  = (const float*)d_in[4];
    const float* sw     = (const float*)d_in[5];
    const float* bias   = (const float*)d_in[6];
    float* out = (float*)d_out;

    const int SMEM = (8192 + 4096 + TROWS + 8) * 4;   // ~48.4 KB -> 3 blocks/SM
    cudaFuncSetAttribute(k_fused, cudaFuncAttributeMaxDynamicSharedMemorySize, SMEM);

    k_fused<<<GRID, NTHR, SMEM>>>(inp, dep, ei, weight, wcomp, sw, bias, out);
}